// round 2
// baseline (speedup 1.0000x reference)
#include <cuda_runtime.h>
#include <math.h>

#define B 64
#define P 8732
#define M 16
#define C 81
#define EPSF 1e-7f

// ---------------- device scratch (static globals: no allocation) ----------------
__device__ float          g_ovl[B * P];       // best overlap per prior
__device__ unsigned char  g_obj[B * P];       // best object per prior (0..15)
__device__ unsigned char  g_tc[B * P];        // true class per prior (0..80)
__device__ float          g_conf_neg[B * P];  // CE loss, zeroed at positives
__device__ int            g_n_pos[B];
__device__ double         g_conf_pos[B];
__device__ double         g_loc_sum;
__device__ double         g_hard_sum;

// ---------------- helpers ----------------
__device__ __forceinline__ double blockReduceSumD(double v) {
    __shared__ double sh[32];
    int lane = threadIdx.x & 31, wid = threadIdx.x >> 5;
    #pragma unroll
    for (int o = 16; o; o >>= 1) v += __shfl_down_sync(0xffffffffu, v, o);
    if (lane == 0) sh[wid] = v;
    __syncthreads();
    int nw = (blockDim.x + 31) >> 5;
    v = (threadIdx.x < (unsigned)nw) ? sh[threadIdx.x] : 0.0;
    if (wid == 0) {
        #pragma unroll
        for (int o = 16; o; o >>= 1) v += __shfl_down_sync(0xffffffffu, v, o);
    }
    return v;  // valid in thread 0
}

// ---------------- K0: zero accumulators ----------------
__global__ void __launch_bounds__(128) k_init() {
    int t = threadIdx.x;
    if (t < B) g_conf_pos[t] = 0.0;
    if (t == B)     g_loc_sum = 0.0;
    if (t == B + 1) g_hard_sum = 0.0;
}

// ---------------- K1: matcher + loc loss (1 block per batch, 256 thr) ----------------
#define ASSIGN_THREADS 256
__global__ void __launch_bounds__(ASSIGN_THREADS)
k_assign(const float4* __restrict__ locs,
         const float4* __restrict__ boxes,
         const int*    __restrict__ labels,
         const float4* __restrict__ priors) {
    const int b = blockIdx.x;
    const int tid = threadIdx.x;
    const int nthr = ASSIGN_THREADS;

    __shared__ float4 sbox[M];
    __shared__ float  sarea[M];
    __shared__ int    slab[M];
    if (tid < M) {
        float4 bx = boxes[b * M + tid];
        sbox[tid]  = bx;
        sarea[tid] = (bx.z - bx.x) * (bx.w - bx.y);
        slab[tid]  = labels[b * M + tid];
    }
    __syncthreads();

    // per-object running best (first-occurrence argmax over priors)
    float best_v[M];
    int   best_p[M];
    #pragma unroll
    for (int m = 0; m < M; m++) { best_v[m] = -1.0f; best_p[m] = 0x7fffffff; }

    float*         ovl = g_ovl + b * P;
    unsigned char* obj = g_obj + b * P;

    for (int p = tid; p < P; p += nthr) {
        float4 pc = priors[p];
        float px0 = pc.x - pc.z * 0.5f;
        float py0 = pc.y - pc.w * 0.5f;
        float px1 = pc.x + pc.z * 0.5f;
        float py1 = pc.y + pc.w * 0.5f;
        float areap = (px1 - px0) * (py1 - py0);
        float bv = -1.0f; int bm = 0;
        #pragma unroll
        for (int m = 0; m < M; m++) {
            float4 bx = sbox[m];
            float iw = fmaxf(fminf(bx.z, px1) - fmaxf(bx.x, px0), 0.0f);
            float ih = fmaxf(fminf(bx.w, py1) - fmaxf(bx.y, py0), 0.0f);
            float inter = iw * ih;
            float iou = inter / (sarea[m] + areap - inter);
            if (iou > bv) { bv = iou; bm = m; }           // first-max over m
            if (iou > best_v[m]) { best_v[m] = iou; best_p[m] = p; }  // p ascending in-thread
        }
        ovl[p] = bv;
        obj[p] = (unsigned char)bm;
    }

    // block reduction of per-object best (max, first index on ties)
    __shared__ float rv[M][ASSIGN_THREADS / 32];
    __shared__ int   rp[M][ASSIGN_THREADS / 32];
    int lane = tid & 31, wid = tid >> 5;
    #pragma unroll
    for (int m = 0; m < M; m++) {
        float v = best_v[m]; int pi = best_p[m];
        #pragma unroll
        for (int o = 16; o; o >>= 1) {
            float ov = __shfl_down_sync(0xffffffffu, v, o);
            int   op = __shfl_down_sync(0xffffffffu, pi, o);
            if (ov > v || (ov == v && op < pi)) { v = ov; pi = op; }
        }
        if (lane == 0) { rv[m][wid] = v; rp[m][wid] = pi; }
    }
    __syncthreads();

    // sequential scatter (matches jnp .at[].set in-order, last-wins; faithful j_idx bug)
    if (tid == 0) {
        const int nw = ASSIGN_THREADS / 32;
        int j = -1;
        for (int m = 0; m < M; m++) {
            float v = rv[m][0]; int pi = rp[m][0];
            for (int w = 1; w < nw; w++)
                if (rv[m][w] > v || (rv[m][w] == v && rp[m][w] < pi)) { v = rv[m][w]; pi = rp[m][w]; }
            if (v > 0.0f) { j++; ovl[pi] = 1.0f; obj[pi] = (unsigned char)j; }
        }
    }
    __syncthreads();

    // labels per prior, positive count, loc loss (self-DIoU) over positives
    int pos_cnt = 0;
    double loc_acc = 0.0;
    const float4* lrow = locs + b * P;
    for (int p = tid; p < P; p += nthr) {
        float ov = ovl[p];
        int tc = (ov < 0.5f) ? 0 : slab[obj[p]];
        g_tc[b * P + p] = (unsigned char)tc;
        if (tc > 0) {
            pos_cnt++;
            float4 bx = lrow[p];
            float iw = fmaxf(bx.z - bx.x, 0.0f);
            float ih = fmaxf(bx.w - bx.y, 0.0f);
            float inter = iw * ih;
            float area = (bx.z - bx.x) * (bx.w - bx.y);
            float iou = inter / (area + area - inter + EPSF);
            // inter_diag == 0 exactly (identical centers); 0/(outer+eps) == 0
            float dious = fminf(fmaxf(iou, -1.0f), 1.0f);
            loc_acc += (double)(1.0f - dious);
        }
    }
    double loc = blockReduceSumD(loc_acc);
    __syncthreads();
    double pc = blockReduceSumD((double)pos_cnt);
    if (tid == 0) {
        g_n_pos[b] = (int)(pc + 0.5);
        atomicAdd(&g_loc_sum, loc);
    }
}

// ---------------- K2: per-prior CE (warp per prior; dominant, HBM-bound) ----------------
__global__ void __launch_bounds__(256)
k_conf(const float* __restrict__ scores) {
    const int warp = blockIdx.x * (blockDim.x >> 5) + (threadIdx.x >> 5);
    const int lane = threadIdx.x & 31;
    if (warp >= B * P) return;
    const float* row = scores + (size_t)warp * C;
    float x0 = row[lane];
    float x1 = row[lane + 32];
    float x2 = (lane < C - 64) ? row[lane + 64] : -INFINITY;
    float m = fmaxf(x0, fmaxf(x1, x2));
    #pragma unroll
    for (int o = 16; o; o >>= 1) m = fmaxf(m, __shfl_xor_sync(0xffffffffu, m, o));
    float s = expf(x0 - m) + expf(x1 - m);
    if (lane < C - 64) s += expf(x2 - m);
    #pragma unroll
    for (int o = 16; o; o >>= 1) s += __shfl_xor_sync(0xffffffffu, s, o);
    int tc = g_tc[warp];
    float conf = m + logf(s) - row[tc];   // = -(log_softmax[tc]); >= 0 always
    if (lane == 0) {
        bool pos = tc > 0;
        g_conf_neg[warp] = pos ? 0.0f : conf;
        if (pos) atomicAdd(&g_conf_pos[warp / P], (double)conf);
    }
}

// ---------------- K3: per-batch sum of 3*n_pos largest conf_neg (radix select) ----------------
__global__ void __launch_bounds__(256) k_topk() {
    const int b = blockIdx.x;
    const int tid = threadIdx.x;  // 256
    const float* vals = g_conf_neg + b * P;
    long long k = 3LL * (long long)g_n_pos[b];
    if (k <= 0) return;
    double sum = 0.0;
    if (k >= P) {
        for (int p = tid; p < P; p += 256) sum += (double)vals[p];
        double tot = blockReduceSumD(sum);
        if (tid == 0) atomicAdd(&g_hard_sum, tot);
        return;
    }
    __shared__ int hist[256];
    __shared__ unsigned int s_pref;
    __shared__ int s_k;
    unsigned int prefix = 0;
    int kk = (int)k;
    for (int pass = 3; pass >= 0; pass--) {
        hist[tid] = 0;
        __syncthreads();
        for (int p = tid; p < P; p += 256) {
            unsigned int v = __float_as_uint(vals[p]);
            bool match = (pass == 3) ? true : ((v >> ((pass + 1) * 8)) == prefix);
            if (match) atomicAdd(&hist[(v >> (pass * 8)) & 255], 1);
        }
        __syncthreads();
        if (tid == 0) {
            int cum = 0; int bin;
            for (bin = 255; bin > 0; bin--) {
                if (cum + hist[bin] >= kk) break;
                cum += hist[bin];
            }
            s_pref = (prefix << 8) | (unsigned int)bin;
            s_k = kk - cum;
        }
        __syncthreads();
        prefix = s_pref; kk = s_k;
        __syncthreads();
    }
    // kk values equal the k-th largest value (bit pattern = prefix); rest strictly greater
    unsigned int thr = prefix;
    for (int p = tid; p < P; p += 256) {
        float fv = vals[p];
        if (__float_as_uint(fv) > thr) sum += (double)fv;
    }
    double tot = blockReduceSumD(sum);
    if (tid == 0) {
        tot += (double)kk * (double)__uint_as_float(thr);
        atomicAdd(&g_hard_sum, tot);
    }
}

// ---------------- K4: combine ----------------
__global__ void __launch_bounds__(64) k_final(float* __restrict__ out) {
    int t = threadIdx.x;  // 64 threads (2 warps)
    __shared__ double scp[2];
    __shared__ int    snp[2];
    double cp = (t < B) ? g_conf_pos[t] : 0.0;
    int    np = (t < B) ? g_n_pos[t]   : 0;
    #pragma unroll
    for (int o = 16; o; o >>= 1) {
        cp += __shfl_down_sync(0xffffffffu, cp, o);
        np += __shfl_down_sync(0xffffffffu, np, o);
    }
    if ((t & 31) == 0) { scp[t >> 5] = cp; snp[t >> 5] = np; }
    __syncthreads();
    if (t == 0) {
        double cps  = scp[0] + scp[1];
        double npos = (double)(snp[0] + snp[1]);
        float conf_loss = (float)((g_hard_sum + cps) / npos);
        float loc_loss  = (float)(g_loc_sum / fmax(npos, 1.0));
        out[0] = conf_loss + loc_loss;  // ALPHA = 1.0
    }
}

// ---------------- launch ----------------
extern "C" void kernel_launch(void* const* d_in, const int* in_sizes, int n_in,
                              void* d_out, int out_size) {
    const float* locs   = (const float*)d_in[0];  // [B,P,4]
    const float* scores = (const float*)d_in[1];  // [B,P,C]
    const float* boxes  = (const float*)d_in[2];  // [B,M,4]
    const int*   labels = (const int*)  d_in[3];  // [B,M]
    const float* priors = (const float*)d_in[4];  // [P,4]
    float* out = (float*)d_out;

    k_init<<<1, 128>>>();
    k_assign<<<B, ASSIGN_THREADS>>>((const float4*)locs, (const float4*)boxes, labels, (const float4*)priors);
    const int total_warps = B * P;
    const int wpb = 8;  // 256 threads
    k_conf<<<(total_warps + wpb - 1) / wpb, 256>>>(scores);
    k_topk<<<B, 256>>>();
    k_final<<<1, 64>>>(out);
}

// round 3
// speedup vs baseline: 1.4769x; 1.4769x over previous
#include <cuda_runtime.h>
#include <math.h>

#define B 64
#define P 8732
#define M 16
#define C 81
#define EPSF 1e-7f
#define L2E 1.4426950408889634f
#define LN2 0.6931471805599453f

// ---------------- device scratch (static globals: no allocation) ----------------
__device__ unsigned char  g_tc[B * P];        // true class per prior (0..80)
__device__ float          g_conf_neg[B * P];  // CE loss, zeroed at positives
__device__ int            g_n_pos[B];
__device__ double         g_conf_pos[B];
__device__ double         g_loc_pb[B];
__device__ double         g_hard_pb[B];
__device__ unsigned int   g_done;

// ---------------- helpers ----------------
__device__ __forceinline__ double blockReduceSumD(double v) {
    __shared__ double sh[32];
    int lane = threadIdx.x & 31, wid = threadIdx.x >> 5;
    #pragma unroll
    for (int o = 16; o; o >>= 1) v += __shfl_down_sync(0xffffffffu, v, o);
    if (lane == 0) sh[wid] = v;
    __syncthreads();
    int nw = (blockDim.x + 31) >> 5;
    v = (threadIdx.x < (unsigned)nw) ? sh[threadIdx.x] : 0.0;
    if (wid == 0) {
        #pragma unroll
        for (int o = 16; o; o >>= 1) v += __shfl_down_sync(0xffffffffu, v, o);
    }
    __syncthreads();
    return v;  // valid in thread 0
}

// ---------------- K1: matcher + loc loss (1 block per batch, 256 thr) ----------------
#define ASSIGN_THREADS 256
__global__ void __launch_bounds__(ASSIGN_THREADS)
k_assign(const float4* __restrict__ locs,
         const float4* __restrict__ boxes,
         const int*    __restrict__ labels,
         const float4* __restrict__ priors,
         float*        __restrict__ ovl_buf,     // reuse of g_conf_neg space not possible; separate buffer below
         unsigned char* __restrict__ obj_buf) {
    const int b = blockIdx.x;
    const int tid = threadIdx.x;
    const int nthr = ASSIGN_THREADS;

    // per-replay init of accumulators owned by this batch
    if (tid == 0) {
        g_conf_pos[b] = 0.0;
        if (b == 0) g_done = 0u;
    }

    __shared__ float4 sbox[M];
    __shared__ float  sarea[M];
    __shared__ int    slab[M];
    if (tid < M) {
        float4 bx = boxes[b * M + tid];
        sbox[tid]  = bx;
        sarea[tid] = (bx.z - bx.x) * (bx.w - bx.y);
        slab[tid]  = labels[b * M + tid];
    }
    __syncthreads();

    // per-object running best (first-occurrence argmax over priors)
    float best_v[M];
    int   best_p[M];
    #pragma unroll
    for (int m = 0; m < M; m++) { best_v[m] = -1.0f; best_p[m] = 0x7fffffff; }

    float*         ovl = ovl_buf + b * P;
    unsigned char* obj = obj_buf + b * P;

    for (int p = tid; p < P; p += nthr) {
        float4 pc = priors[p];
        float px0 = pc.x - pc.z * 0.5f;
        float py0 = pc.y - pc.w * 0.5f;
        float px1 = pc.x + pc.z * 0.5f;
        float py1 = pc.y + pc.w * 0.5f;
        float areap = (px1 - px0) * (py1 - py0);
        float bv = -1.0f; int bm = 0;
        #pragma unroll
        for (int m = 0; m < M; m++) {
            float4 bx = sbox[m];
            float iw = fmaxf(fminf(bx.z, px1) - fmaxf(bx.x, px0), 0.0f);
            float ih = fmaxf(fminf(bx.w, py1) - fmaxf(bx.y, py0), 0.0f);
            float inter = iw * ih;
            float iou = __fdividef(inter, sarea[m] + areap - inter);
            if (iou > bv) { bv = iou; bm = m; }           // first-max over m
            if (iou > best_v[m]) { best_v[m] = iou; best_p[m] = p; }  // p ascending in-thread
        }
        ovl[p] = bv;
        obj[p] = (unsigned char)bm;
    }

    // block reduction of per-object best (max, first index on ties)
    __shared__ float rv[M][ASSIGN_THREADS / 32];
    __shared__ int   rp[M][ASSIGN_THREADS / 32];
    int lane = tid & 31, wid = tid >> 5;
    #pragma unroll
    for (int m = 0; m < M; m++) {
        float v = best_v[m]; int pi = best_p[m];
        #pragma unroll
        for (int o = 16; o; o >>= 1) {
            float ov = __shfl_down_sync(0xffffffffu, v, o);
            int   op = __shfl_down_sync(0xffffffffu, pi, o);
            if (ov > v || (ov == v && op < pi)) { v = ov; pi = op; }
        }
        if (lane == 0) { rv[m][wid] = v; rp[m][wid] = pi; }
    }
    __syncthreads();

    // sequential scatter (matches jnp .at[].set in-order, last-wins; faithful j_idx bug)
    if (tid == 0) {
        const int nw = ASSIGN_THREADS / 32;
        int j = -1;
        for (int m = 0; m < M; m++) {
            float v = rv[m][0]; int pi = rp[m][0];
            for (int w = 1; w < nw; w++)
                if (rv[m][w] > v || (rv[m][w] == v && rp[m][w] < pi)) { v = rv[m][w]; pi = rp[m][w]; }
            if (v > 0.0f) { j++; ovl[pi] = 1.0f; obj[pi] = (unsigned char)j; }
        }
    }
    __syncthreads();

    // labels per prior, positive count, loc loss (self-DIoU) over positives
    int pos_cnt = 0;
    double loc_acc = 0.0;
    const float4* lrow = locs + b * P;
    for (int p = tid; p < P; p += nthr) {
        float ov = ovl[p];
        int tc = (ov < 0.5f) ? 0 : slab[obj[p]];
        g_tc[b * P + p] = (unsigned char)tc;
        if (tc > 0) {
            pos_cnt++;
            float4 bx = lrow[p];
            float iw = fmaxf(bx.z - bx.x, 0.0f);
            float ih = fmaxf(bx.w - bx.y, 0.0f);
            float inter = iw * ih;
            float area = (bx.z - bx.x) * (bx.w - bx.y);
            float iou = __fdividef(inter, area + area - inter + EPSF);
            // inter_diag == 0 exactly (identical centers); 0/(outer+eps) == 0
            float dious = fminf(fmaxf(iou, -1.0f), 1.0f);
            loc_acc += (double)(1.0f - dious);
        }
    }
    double loc = blockReduceSumD(loc_acc);
    double pc = blockReduceSumD((double)pos_cnt);
    if (tid == 0) {
        g_n_pos[b]  = (int)(pc + 0.5);
        g_loc_pb[b] = loc;
    }
}

// scratch for assign (can't alias g_conf_neg: g_conf_neg written later anyway, but ovl needed only inside assign)
__device__ float          g_ovl[B * P];
__device__ unsigned char  g_obj[B * P];

// ---------------- K2: per-prior CE (warp per prior; dominant, HBM-bound) ----------------
__global__ void __launch_bounds__(256)
k_conf(const float* __restrict__ scores) {
    const int warp = blockIdx.x * (blockDim.x >> 5) + (threadIdx.x >> 5);
    const int lane = threadIdx.x & 31;
    if (warp >= B * P) return;
    const float* row = scores + (size_t)warp * C;
    float x0 = row[lane];
    float x1 = row[lane + 32];
    float x2 = (lane < C - 64) ? row[lane + 64] : -INFINITY;
    float m = fmaxf(x0, fmaxf(x1, x2));
    #pragma unroll
    for (int o = 16; o; o >>= 1) m = fmaxf(m, __shfl_xor_sync(0xffffffffu, m, o));
    float s = exp2f((x0 - m) * L2E) + exp2f((x1 - m) * L2E);
    if (lane < C - 64) s += exp2f((x2 - m) * L2E);
    #pragma unroll
    for (int o = 16; o; o >>= 1) s += __shfl_xor_sync(0xffffffffu, s, o);
    int tc = g_tc[warp];
    float conf = fmaf(log2f(s), LN2, m) - row[tc];   // = -(log_softmax[tc]); >= 0 always
    if (lane == 0) {
        bool pos = tc > 0;
        g_conf_neg[warp] = pos ? 0.0f : conf;
        if (pos) atomicAdd(&g_conf_pos[warp / P], (double)conf);
    }
}

// ---------------- K3: per-batch top-k sum (smem-cached radix select) + fused final ----------------
__global__ void __launch_bounds__(256)
k_topk(float* __restrict__ out) {
    const int b = blockIdx.x;
    const int tid = threadIdx.x;  // 256
    const int lane = tid & 31;

    __shared__ unsigned int sv[P];     // 34928 B
    __shared__ int hist[256];
    __shared__ int s_bin, s_kk;
    __shared__ int s_last;

    // cache values once
    const float* vals = g_conf_neg + b * P;
    for (int p = tid; p < P; p += 256) sv[p] = __float_as_uint(vals[p]);
    __syncthreads();

    long long k = 3LL * (long long)g_n_pos[b];
    double result = 0.0;

    if (k >= P) {
        double sum = 0.0;
        for (int p = tid; p < P; p += 256) sum += (double)__uint_as_float(sv[p]);
        result = blockReduceSumD(sum);
    } else if (k > 0) {
        unsigned int prefix = 0;
        int kk = (int)k;
        for (int pass = 3; pass >= 0; pass--) {
            const int sh_lo = pass * 8;
            hist[tid] = 0;
            __syncthreads();
            // warp-aggregated histogram
            for (int base = 0; base < P; base += 256) {
                int p = base + tid;
                bool in = p < P;
                unsigned int v = in ? sv[p] : 0u;
                bool match = in && (pass == 3 || (v >> (sh_lo + 8)) == prefix);
                unsigned int act = __ballot_sync(0xffffffffu, match);
                if (match) {
                    unsigned int bin = (v >> sh_lo) & 255u;
                    unsigned int peers = __match_any_sync(act, bin);
                    if ((__ffs(peers) - 1) == lane)
                        atomicAdd(&hist[bin], (int)__popc(peers));
                }
            }
            __syncthreads();
            // parallel inclusive suffix sum over 256 bins
            int v = hist[tid];
            #pragma unroll
            for (int off = 1; off < 256; off <<= 1) {
                int u = (tid + off < 256) ? hist[tid + off] : 0;
                __syncthreads();
                hist[tid] = v = v + u;
                __syncthreads();
            }
            // select bin: cnt_ge[bin] >= kk  &&  cnt_ge[bin+1] < kk
            int cge  = hist[tid];
            int cge1 = (tid < 255) ? hist[tid + 1] : 0;
            if (cge >= kk && (tid == 255 || cge1 < kk)) { s_bin = tid; s_kk = kk - cge1; }
            __syncthreads();
            prefix = (prefix << 8) | (unsigned int)s_bin;
            kk = s_kk;
            __syncthreads();
        }
        // kk values equal the k-th largest; values strictly above prefix all included
        unsigned int thr = prefix;
        double sum = 0.0;
        for (int p = tid; p < P; p += 256) {
            unsigned int v = sv[p];
            if (v > thr) sum += (double)__uint_as_float(v);
        }
        result = blockReduceSumD(sum);
        if (tid == 0) result += (double)kk * (double)__uint_as_float(thr);
    }
    if (tid == 0) g_hard_pb[b] = result;

    // ---- fused final: last block combines everything ----
    __threadfence();
    if (tid == 0) {
        unsigned int t = atomicAdd(&g_done, 1u);
        s_last = (t == B - 1u) ? 1 : 0;
    }
    __syncthreads();
    if (s_last) {
        double cp = 0.0, hs = 0.0, ls = 0.0;
        long long np = 0;
        if (tid < B) {
            cp = g_conf_pos[tid];
            hs = g_hard_pb[tid];
            ls = g_loc_pb[tid];
            np = g_n_pos[tid];
        }
        double cps = blockReduceSumD(cp);
        double hss = blockReduceSumD(hs);
        double lss = blockReduceSumD(ls);
        double nps = blockReduceSumD((double)np);
        if (tid == 0) {
            float conf_loss = (float)((hss + cps) / nps);
            float loc_loss  = (float)(lss / fmax(nps, 1.0));
            out[0] = conf_loss + loc_loss;  // ALPHA = 1.0
        }
    }
}

// ---------------- launch ----------------
extern "C" void kernel_launch(void* const* d_in, const int* in_sizes, int n_in,
                              void* d_out, int out_size) {
    const float* locs   = (const float*)d_in[0];  // [B,P,4]
    const float* scores = (const float*)d_in[1];  // [B,P,C]
    const float* boxes  = (const float*)d_in[2];  // [B,M,4]
    const int*   labels = (const int*)  d_in[3];  // [B,M]
    const float* priors = (const float*)d_in[4];  // [P,4]
    float* out = (float*)d_out;

    float* ovl_ptr; unsigned char* obj_ptr;
    cudaGetSymbolAddress((void**)&ovl_ptr, g_ovl);
    cudaGetSymbolAddress((void**)&obj_ptr, g_obj);

    k_assign<<<B, ASSIGN_THREADS>>>((const float4*)locs, (const float4*)boxes, labels,
                                    (const float4*)priors, ovl_ptr, obj_ptr);
    const int total_warps = B * P;
    const int wpb = 8;  // 256 threads
    k_conf<<<(total_warps + wpb - 1) / wpb, 256>>>(scores);
    k_topk<<<B, 256>>>(out);
}